// round 12
// baseline (speedup 1.0000x reference)
#include <cuda_runtime.h>
#include <cstdint>

#define IN_FEAT 3072
#define PADDED  4096
#define M_ROWS  8192
#define N_COLS  4096
#define K_DIM   4096

#define BM 128
#define BNT 128              // tensor columns (warps 8-15: hi-wid priority)
#define BND 128              // dp4a columns (warps 0-7)
#define BN (BNT + BND)       // 256 -- divides N_COLS exactly
#define BK 64
#define NSTAGE 8             // 4 pair-slots x 2 chunks
#define NITER (K_DIM / BK)   // 64
#define NPAIR (NITER / 2)    // 32
#define NTHREADS 512

#define A_STAGE 8192                        // 128 rows x 64 B
#define B_STAGE (BN * BK)                   // 256 rows x 64 B = 16384
#define SMEM_B_OFF (NSTAGE * A_STAGE)       // 65536
#define SMEM_TOTAL (NSTAGE * (A_STAGE + B_STAGE))   // 196608
#define PAIR_SEGS (2 * (BM + BN) * 4)       // 3072 16B segments per pair

// -------- device scratch (static globals: no allocations allowed) ----------
__device__ int8_t g_zx[(size_t)M_ROWS * K_DIM];   // 32 MB
__device__ int8_t g_zw[(size_t)N_COLS * K_DIM];   // 16 MB
__device__ float  g_alpha[M_ROWS];
__device__ float  g_beta[N_COLS];

// -------- helpers -----------------------------------------------------------
__device__ __forceinline__ uint32_t smem_u32(const void* p) {
    uint32_t a;
    asm("{ .reg .u64 t; cvta.to.shared.u64 t, %1; cvt.u32.u64 %0, t; }"
        : "=r"(a) : "l"(p));
    return a;
}

__device__ __forceinline__ void cpa16(uint32_t sdst, const void* gsrc) {
    asm volatile("cp.async.cg.shared.global [%0], [%1], 16;" :: "r"(sdst), "l"(gsrc));
}

__device__ __forceinline__ void ldm4(uint32_t addr, uint32_t& r0, uint32_t& r1,
                                     uint32_t& r2, uint32_t& r3) {
    asm volatile("ldmatrix.sync.aligned.m8n8.x4.shared.b16 {%0,%1,%2,%3}, [%4];"
                 : "=r"(r0), "=r"(r1), "=r"(r2), "=r"(r3) : "r"(addr));
}

__device__ __forceinline__ void mma_s8(int* d, const uint32_t* a, uint32_t b0, uint32_t b1) {
    asm volatile(
        "mma.sync.aligned.m16n8k32.row.col.s32.s8.s8.s32 "
        "{%0,%1,%2,%3}, {%4,%5,%6,%7}, {%8,%9}, {%0,%1,%2,%3};"
        : "+r"(d[0]), "+r"(d[1]), "+r"(d[2]), "+r"(d[3])
        : "r"(a[0]), "r"(a[1]), "r"(a[2]), "r"(a[3]), "r"(b0), "r"(b1));
}

__device__ __forceinline__ uint4 lds128(uint32_t addr) {
    uint4 v;
    asm volatile("ld.shared.v4.u32 {%0,%1,%2,%3}, [%4];"
                 : "=r"(v.x), "=r"(v.y), "=r"(v.z), "=r"(v.w) : "r"(addr));
    return v;
}

__device__ __forceinline__ int dp4a_s(uint32_t a, uint32_t b, int c) {
    int d;
    asm("dp4a.s32.s32 %0, %1, %2, %3;" : "=r"(d) : "r"(a), "r"(b), "r"(c));
    return d;
}

// swizzle for 64-byte rows at 16B granules (cp.async / ldmatrix / LDS.128 safe)
#define SWZ64(row, c) (((uint32_t)(row) << 6) + ((((c) ^ (((row) >> 1) & 3)) & 3) << 4))

// ============================================================================
// Kernel 1: per-row pad -> FWHT(4096) -> quantize (z = q-128, int8) -> row sum
// ============================================================================
__global__ void __launch_bounds__(256)
hq_fwht_quant(const float* __restrict__ x, const float* __restrict__ w,
              const float* __restrict__ bias, float kA, float c2) {
    __shared__ float xch[PADDED];
    __shared__ float wsum[8];

    int row = blockIdx.x;
    int mode = (row >= M_ROWS);
    if (mode) row -= M_ROWS;
    const float* in = mode ? (w + (size_t)row * IN_FEAT) : (x + (size_t)row * IN_FEAT);
    const int t = threadIdx.x;

    float v[16];
    if (t < IN_FEAT / 16) {
        const float4* p = (const float4*)(in + t * 16);
        float4 a0 = p[0], a1 = p[1], a2 = p[2], a3 = p[3];
        v[0]=a0.x; v[1]=a0.y; v[2]=a0.z; v[3]=a0.w;
        v[4]=a1.x; v[5]=a1.y; v[6]=a1.z; v[7]=a1.w;
        v[8]=a2.x; v[9]=a2.y; v[10]=a2.z; v[11]=a2.w;
        v[12]=a3.x; v[13]=a3.y; v[14]=a3.z; v[15]=a3.w;
    } else {
        #pragma unroll
        for (int e = 0; e < 16; ++e) v[e] = 0.0f;
    }

    #pragma unroll
    for (int st = 1; st < 16; st <<= 1) {
        #pragma unroll
        for (int e = 0; e < 16; ++e)
            if (!(e & st)) {
                float a = v[e], b = v[e | st];
                v[e] = a + b;
                v[e | st] = a - b;
            }
    }
    #pragma unroll
    for (int b = 1; b <= 16; b <<= 1) {
        bool up = (t & b) != 0;
        #pragma unroll
        for (int e = 0; e < 16; ++e) {
            float o = __shfl_xor_sync(0xffffffffu, v[e], b, 32);
            v[e] = up ? (o - v[e]) : (v[e] + o);
        }
    }
    #pragma unroll
    for (int b = 32; b <= 128; b <<= 1) {
        __syncthreads();
        #pragma unroll
        for (int e = 0; e < 16; ++e) xch[e * 256 + t] = v[e];
        __syncthreads();
        int pt = t ^ b;
        bool up = (t & b) != 0;
        #pragma unroll
        for (int e = 0; e < 16; ++e) {
            float o = xch[e * 256 + pt];
            v[e] = up ? (o - v[e]) : (v[e] + o);
        }
    }

    const float inv_qs = 255.0f / 768.0f;
    int zi[16];
    float zsum = 0.0f;
    #pragma unroll
    for (int e = 0; e < 16; ++e) {
        float u = fminf(fmaxf(v[e], -384.0f), 384.0f);
        float q = fminf(fmaxf(rintf((u + 384.0f) * inv_qs), 0.0f), 255.0f);
        zi[e] = (int)q - 128;
        zsum += (float)zi[e];
    }
    uint32_t pk[4];
    #pragma unroll
    for (int j = 0; j < 4; ++j)
        pk[j] = (uint32_t)(zi[4*j] & 0xff) | ((uint32_t)(zi[4*j+1] & 0xff) << 8) |
                ((uint32_t)(zi[4*j+2] & 0xff) << 16) | ((uint32_t)(zi[4*j+3] & 0xff) << 24);
    int8_t* oz = (mode ? g_zw : g_zx) + (size_t)row * PADDED + t * 16;
    *(uint4*)oz = make_uint4(pk[0], pk[1], pk[2], pk[3]);

    #pragma unroll
    for (int off = 16; off > 0; off >>= 1)
        zsum += __shfl_down_sync(0xffffffffu, zsum, off, 32);
    if ((t & 31) == 0) wsum[t >> 5] = zsum;
    __syncthreads();
    if (t == 0) {
        float S = 0.0f;
        #pragma unroll
        for (int i = 0; i < 8; ++i) S += wsum[i];
        float stat = kA * S;
        if (mode) g_beta[row] = stat + c2 + bias[row];
        else      g_alpha[row] = stat;
    }
}

// ============================================================================
// Kernel 2: warp-specialized hybrid GEMM, tile 128 x 256.
//   warps 0-7  : dp4a (fma pipe), cols 128..255   [low wid: backfill]
//   warps 8-15 : mma.sync (tensor pipe), cols 0..127 [hi wid: arbiter priority]
// 8 smem stages = 4 pair-slots, prefetch distance 3 pairs, loads AFTER sync.
// ============================================================================
__device__ __forceinline__ void load_pair(uint32_t sb, const int8_t* Ag, const int8_t* Bg,
                                          int pair, int tid) {
    const int s0 = (pair & 3) * 2;
    const int k0 = pair * 2 * BK;
    #pragma unroll
    for (int j = 0; j < PAIR_SEGS / NTHREADS; ++j) {   // 3072/512 = 6
        int seg = tid + NTHREADS * j;
        int half = (seg >= PAIR_SEGS / 2);
        int seg1 = seg - half * (PAIR_SEGS / 2);
        int s = s0 + half;
        int kh = k0 + half * BK;
        int r = seg1 >> 2, c = seg1 & 3;
        if (r < BM) {
            cpa16(sb + s * A_STAGE + SWZ64(r, c),
                  Ag + (size_t)r * K_DIM + kh + c * 16);
        } else {
            int br = r - BM;
            cpa16(sb + SMEM_B_OFF + s * B_STAGE + SWZ64(br, c),
                  Bg + (size_t)br * K_DIM + kh + c * 16);
        }
    }
}

// wait until pair p arrived, given commits go up to min(p+2, NPAIR-1)
__device__ __forceinline__ void wait_pair(int p) {
    if (p < NPAIR - 2)      asm volatile("cp.async.wait_group 2;" ::: "memory");
    else if (p < NPAIR - 1) asm volatile("cp.async.wait_group 1;" ::: "memory");
    else                    asm volatile("cp.async.wait_group 0;" ::: "memory");
}

__global__ void __launch_bounds__(NTHREADS, 1)
hq_gemm(float* __restrict__ out, float k1) {
    extern __shared__ char smem[];
    const uint32_t sb = smem_u32(smem);
    const int tid = threadIdx.x;
    const int wid = tid >> 5, lane = tid & 31;

    const int m0 = blockIdx.y * BM;
    const int n0 = blockIdx.x * BN;

    const int8_t* Ag = g_zx + (size_t)m0 * K_DIM;
    const int8_t* Bg = g_zw + (size_t)n0 * K_DIM;

    // prologue: pairs 0,1,2 in flight
    #pragma unroll
    for (int i = 0; i < 3; ++i) {
        load_pair(sb, Ag, Bg, i, tid);
        asm volatile("cp.async.commit_group;" ::: "memory");
    }

    if (wid >= 8) {
        // ==================== tensor warps (hi-wid: priority) ============
        const int twid = wid - 8;
        const int warpM = twid & 3, warpN = twid >> 2;

        const int arow = warpM * 32 + (lane & 7) + ((lane >> 3) & 1) * 8;
        const int acadd = (lane >> 4) & 1;
        const int axor = (arow >> 1) & 3;
        const int brow = warpN * 64 + (lane & 7) + ((lane >> 4) & 1) * 8;
        const int bcadd = (lane >> 3) & 1;
        const int bxor = (brow >> 1) & 3;

        int acc[64];
        #pragma unroll
        for (int i = 0; i < 64; ++i) acc[i] = 0;

        for (int p = 0; p < NPAIR; ++p) {
            wait_pair(p);
            __syncthreads();   // pair p visible; all warps done with pair p-1
            if (p + 3 < NPAIR) {
                load_pair(sb, Ag, Bg, p + 3, tid);   // overwrites pair p-1 slot
                asm volatile("cp.async.commit_group;" ::: "memory");
            }

            #pragma unroll
            for (int h = 0; h < 2; ++h) {
                uint32_t aS = sb + ((p & 3) * 2 + h) * A_STAGE;
                uint32_t bS = sb + SMEM_B_OFF + ((p & 3) * 2 + h) * B_STAGE;
                #pragma unroll
                for (int kk = 0; kk < 2; ++kk) {
                    uint32_t af[8], bf[16];
                    #pragma unroll
                    for (int ma = 0; ma < 2; ++ma)
                        ldm4(aS + (uint32_t)(arow + ma * 16) * 64 +
                                 (uint32_t)(((2 * kk + acadd) ^ axor) << 4),
                             af[4*ma], af[4*ma+1], af[4*ma+2], af[4*ma+3]);
                    #pragma unroll
                    for (int nb = 0; nb < 4; ++nb)
                        ldm4(bS + (uint32_t)(brow + nb * 16) * 64 +
                                 (uint32_t)(((2 * kk + bcadd) ^ bxor) << 4),
                             bf[4*nb], bf[4*nb+1], bf[4*nb+2], bf[4*nb+3]);
                    #pragma unroll
                    for (int ma = 0; ma < 2; ++ma)
                        #pragma unroll
                        for (int na = 0; na < 8; ++na)
                            mma_s8(acc + (ma * 8 + na) * 4, af + 4 * ma,
                                   bf[(na >> 1) * 4 + (na & 1) * 2],
                                   bf[(na >> 1) * 4 + (na & 1) * 2 + 1]);
                }
            }
        }

        #pragma unroll
        for (int ma = 0; ma < 2; ++ma) {
            int r0 = m0 + warpM * 32 + ma * 16 + (lane >> 2);
            float al0 = g_alpha[r0], al1 = g_alpha[r0 + 8];
            float* o0 = out + (size_t)r0 * N_COLS;
            float* o1 = out + (size_t)(r0 + 8) * N_COLS;
            #pragma unroll
            for (int na = 0; na < 8; ++na) {
                int col = n0 + warpN * 64 + na * 8 + (lane & 3) * 2;
                float b0 = g_beta[col], b1 = g_beta[col + 1];
                const int* d = acc + (ma * 8 + na) * 4;
                float2 p0, p1;
                p0.x = fmaf(k1, (float)d[0], al0 + b0);
                p0.y = fmaf(k1, (float)d[1], al0 + b1);
                p1.x = fmaf(k1, (float)d[2], al1 + b0);
                p1.y = fmaf(k1, (float)d[3], al1 + b1);
                *(float2*)(o0 + col) = p0;
                *(float2*)(o1 + col) = p1;
            }
        }
    } else {
        // ===== dp4a warps (low wid): 128 cols, 4 rows x 16 cols/thread =====
        const int warpMd = wid & 3;                      // 4 groups x 32 rows
        const int warpNd = wid >> 2;                     // 2 groups x 64 cols
        const int dr0 = warpMd * 32 + (lane >> 2);       // rows dr0 + 8i
        const int db0 = BNT + warpNd * 64 + (lane & 3);  // tile cols db0 + 4j

        int acc2[64];
        #pragma unroll
        for (int i = 0; i < 64; ++i) acc2[i] = 0;

        for (int p = 0; p < NPAIR; ++p) {
            wait_pair(p);
            __syncthreads();
            if (p + 3 < NPAIR) {
                load_pair(sb, Ag, Bg, p + 3, tid);
                asm volatile("cp.async.commit_group;" ::: "memory");
            }

            #pragma unroll
            for (int h = 0; h < 2; ++h) {
                uint32_t aS = sb + ((p & 3) * 2 + h) * A_STAGE;
                uint32_t bS = sb + SMEM_B_OFF + ((p & 3) * 2 + h) * B_STAGE;
                #pragma unroll
                for (int kb = 0; kb < 4; ++kb) {
                    uint4 aw[4];
                    #pragma unroll
                    for (int i = 0; i < 4; ++i) {
                        int r = dr0 + 8 * i;
                        aw[i] = lds128(aS + ((uint32_t)r << 6) +
                                       (uint32_t)((kb ^ ((r >> 1) & 3)) << 4));
                    }
                    #pragma unroll
                    for (int j = 0; j < 16; ++j) {
                        int r = db0 + 4 * j;
                        uint4 bw = lds128(bS + ((uint32_t)r << 6) +
                                          (uint32_t)((kb ^ ((r >> 1) & 3)) << 4));
                        #pragma unroll
                        for (int i = 0; i < 4; ++i) {
                            int a0 = acc2[i * 16 + j];
                            a0 = dp4a_s(aw[i].x, bw.x, a0);
                            a0 = dp4a_s(aw[i].y, bw.y, a0);
                            a0 = dp4a_s(aw[i].z, bw.z, a0);
                            acc2[i * 16 + j] = dp4a_s(aw[i].w, bw.w, a0);
                        }
                    }
                }
            }
        }

        #pragma unroll
        for (int i = 0; i < 4; ++i) {
            int row = m0 + dr0 + 8 * i;
            float al = g_alpha[row];
            float* orow = out + (size_t)row * N_COLS;
            #pragma unroll
            for (int j = 0; j < 16; ++j) {
                int col = n0 + db0 + 4 * j;
                orow[col] = fmaf(k1, (float)acc2[i * 16 + j], al + g_beta[col]);
            }
        }
    }
}

// ============================================================================
extern "C" void kernel_launch(void* const* d_in, const int* in_sizes, int n_in,
                              void* d_out, int out_size) {
    const float* x = (const float*)d_in[0];
    const float* w = (const float*)d_in[1];
    const float* bias = (const float*)d_in[2];
    float* out = (float*)d_out;

    const float scale = 768.0f / 255.0f;
    const float cc = -384.0f + 128.0f * scale;        // = 384/255
    const float k1 = scale * scale / (float)PADDED;
    const float kA = scale * cc / (float)PADDED;
    const float c2 = cc * cc;

    hq_fwht_quant<<<M_ROWS + N_COLS, 256>>>(x, w, bias, kA, c2);

    static_assert(SMEM_TOTAL == 196608, "smem");
    cudaFuncSetAttribute(hq_gemm, cudaFuncAttributeMaxDynamicSharedMemorySize, SMEM_TOTAL);
    dim3 grid(N_COLS / BN, M_ROWS / BM);              // 16 x 64
    hq_gemm<<<grid, NTHREADS, SMEM_TOTAL>>>(out, k1);
}

// round 13
// speedup vs baseline: 1.6965x; 1.6965x over previous
#include <cuda_runtime.h>
#include <cstdint>

#define IN_FEAT 3072
#define PADDED  4096
#define M_ROWS  8192
#define N_COLS  4096
#define K_DIM   4096

#define BM 128
#define BNT 128              // tensor columns (warps 0-7)
#define BND 128              // dp4a columns (warps 8-15)
#define BN (BNT + BND)       // 256 -- divides N_COLS exactly
#define BK 64
#define NSTAGE 6             // 3 pair-slots x 2 chunks
#define NITER (K_DIM / BK)   // 64
#define NPAIR (NITER / 2)    // 32
#define NTHREADS 512

#define A_STAGE 8192                        // 128 rows x 64 B
#define B_STAGE (BN * BK)                   // 256 rows x 64 B = 16384
#define SMEM_B_OFF (NSTAGE * A_STAGE)       // 49152
#define SMEM_TOTAL (NSTAGE * (A_STAGE + B_STAGE))   // 147456
#define PAIR_SEGS (2 * (BM + BN) * 4)       // 3072 16B segments per pair

// -------- device scratch (static globals: no allocations allowed) ----------
__device__ int8_t g_zx[(size_t)M_ROWS * K_DIM];   // 32 MB
__device__ int8_t g_zw[(size_t)N_COLS * K_DIM];   // 16 MB
__device__ float  g_alpha[M_ROWS];
__device__ float  g_beta[N_COLS];

// -------- helpers -----------------------------------------------------------
__device__ __forceinline__ uint32_t smem_u32(const void* p) {
    uint32_t a;
    asm("{ .reg .u64 t; cvta.to.shared.u64 t, %1; cvt.u32.u64 %0, t; }"
        : "=r"(a) : "l"(p));
    return a;
}

__device__ __forceinline__ void cpa16(uint32_t sdst, const void* gsrc) {
    asm volatile("cp.async.cg.shared.global [%0], [%1], 16;" :: "r"(sdst), "l"(gsrc));
}

__device__ __forceinline__ void ldm4(uint32_t addr, uint32_t& r0, uint32_t& r1,
                                     uint32_t& r2, uint32_t& r3) {
    asm volatile("ldmatrix.sync.aligned.m8n8.x4.shared.b16 {%0,%1,%2,%3}, [%4];"
                 : "=r"(r0), "=r"(r1), "=r"(r2), "=r"(r3) : "r"(addr));
}

__device__ __forceinline__ void mma_s8(int* d, const uint32_t* a, uint32_t b0, uint32_t b1) {
    asm volatile(
        "mma.sync.aligned.m16n8k32.row.col.s32.s8.s8.s32 "
        "{%0,%1,%2,%3}, {%4,%5,%6,%7}, {%8,%9}, {%0,%1,%2,%3};"
        : "+r"(d[0]), "+r"(d[1]), "+r"(d[2]), "+r"(d[3])
        : "r"(a[0]), "r"(a[1]), "r"(a[2]), "r"(a[3]), "r"(b0), "r"(b1));
}

__device__ __forceinline__ uint4 lds128(uint32_t addr) {
    uint4 v;
    asm volatile("ld.shared.v4.u32 {%0,%1,%2,%3}, [%4];"
                 : "=r"(v.x), "=r"(v.y), "=r"(v.z), "=r"(v.w) : "r"(addr));
    return v;
}

__device__ __forceinline__ int dp4a_s(uint32_t a, uint32_t b, int c) {
    int d;
    asm("dp4a.s32.s32 %0, %1, %2, %3;" : "=r"(d) : "r"(a), "r"(b), "r"(c));
    return d;
}

// swizzle for 64-byte rows at 16B granules (cp.async / ldmatrix / LDS.128 safe)
#define SWZ64(row, c) (((uint32_t)(row) << 6) + ((((c) ^ (((row) >> 1) & 3)) & 3) << 4))

// ============================================================================
// Kernel 1: per-row pad -> FWHT(4096) -> quantize (z = q-128, int8) -> row sum
// Cross-warp stages via ONE smem exchange:
//   write v[e] (element p = 16t + e) -> xch[e*257 + t]      (conflict-free)
//   read  u[j] = element p' = (j>>1)*512 + 2t + (j&1)       (<=2-way conflict)
//   then strides 512/1024/2048 act on j bits 1..3 in registers.
// ============================================================================
__global__ void __launch_bounds__(256)
hq_fwht_quant(const float* __restrict__ x, const float* __restrict__ w,
              const float* __restrict__ bias, float kA, float c2) {
    __shared__ float xch[16 * 257];
    __shared__ float wsum[8];

    int row = blockIdx.x;
    int mode = (row >= M_ROWS);
    if (mode) row -= M_ROWS;
    const float* in = mode ? (w + (size_t)row * IN_FEAT) : (x + (size_t)row * IN_FEAT);
    const int t = threadIdx.x;

    float v[16];
    if (t < IN_FEAT / 16) {
        const float4* p = (const float4*)(in + t * 16);
        float4 a0 = p[0], a1 = p[1], a2 = p[2], a3 = p[3];
        v[0]=a0.x; v[1]=a0.y; v[2]=a0.z; v[3]=a0.w;
        v[4]=a1.x; v[5]=a1.y; v[6]=a1.z; v[7]=a1.w;
        v[8]=a2.x; v[9]=a2.y; v[10]=a2.z; v[11]=a2.w;
        v[12]=a3.x; v[13]=a3.y; v[14]=a3.z; v[15]=a3.w;
    } else {
        #pragma unroll
        for (int e = 0; e < 16; ++e) v[e] = 0.0f;
    }

    // strides 1,2,4,8 (p bits 0-3 = e bits)
    #pragma unroll
    for (int st = 1; st < 16; st <<= 1) {
        #pragma unroll
        for (int e = 0; e < 16; ++e)
            if (!(e & st)) {
                float a = v[e], b = v[e | st];
                v[e] = a + b;
                v[e | st] = a - b;
            }
    }
    // strides 16..256 (p bits 4-8 = t bits 0-4) via shfl
    #pragma unroll
    for (int b = 1; b <= 16; b <<= 1) {
        bool up = (t & b) != 0;
        #pragma unroll
        for (int e = 0; e < 16; ++e) {
            float o = __shfl_xor_sync(0xffffffffu, v[e], b, 32);
            v[e] = up ? (o - v[e]) : (v[e] + o);
        }
    }
    // single exchange for strides 512,1024,2048 (p bits 9-11 = t bits 5-7)
    #pragma unroll
    for (int e = 0; e < 16; ++e) xch[e * 257 + t] = v[e];
    __syncthreads();
    float u[16];
    #pragma unroll
    for (int j = 0; j < 16; ++j) {
        int k = j >> 1, b = j & 1;
        int e0 = ((t & 7) << 1) | b;       // = p' & 15
        int t0 = (k << 5) | (t >> 3);      // = p' >> 4
        u[j] = xch[e0 * 257 + t0];
    }
    // remaining stages: p' bit9 = j bit1, bit10 = j bit2, bit11 = j bit3
    #pragma unroll
    for (int st = 2; st <= 8; st <<= 1) {
        #pragma unroll
        for (int j = 0; j < 16; ++j)
            if (!(j & st)) {
                float a = u[j], c = u[j | st];
                u[j] = a + c;
                u[j | st] = a - c;
            }
    }

    // quantize: q = clip(rint((clip(u,-384,384)+384)/scale),0,255); z = q-128
    const float inv_qs = 255.0f / 768.0f;
    int zi[16];
    float zsum = 0.0f;
    #pragma unroll
    for (int j = 0; j < 16; ++j) {
        float uu = fminf(fmaxf(u[j], -384.0f), 384.0f);
        float q = fminf(fmaxf(rintf((uu + 384.0f) * inv_qs), 0.0f), 255.0f);
        zi[j] = (int)q - 128;
        zsum += (float)zi[j];
    }
    // thread t holds elements p' = k*512 + 2t + b  -> char2 stores (coalesced)
    int8_t* oz = (mode ? g_zw : g_zx) + (size_t)row * PADDED;
    #pragma unroll
    for (int k = 0; k < 8; ++k) {
        char2 val;
        val.x = (char)zi[2 * k];
        val.y = (char)zi[2 * k + 1];
        *(char2*)(oz + (k << 9) + (t << 1)) = val;
    }

    #pragma unroll
    for (int off = 16; off > 0; off >>= 1)
        zsum += __shfl_down_sync(0xffffffffu, zsum, off, 32);
    if ((t & 31) == 0) wsum[t >> 5] = zsum;
    __syncthreads();
    if (t == 0) {
        float S = 0.0f;
        #pragma unroll
        for (int i = 0; i < 8; ++i) S += wsum[i];
        float stat = kA * S;
        if (mode) g_beta[row] = stat + c2 + bias[row];
        else      g_alpha[row] = stat;
    }
}

// ============================================================================
// Kernel 2 (exact R11 structure): warp-specialized hybrid GEMM, tile 128x256.
//   warps 0-7  : mma.sync (tensor pipe), cols 0..127
//   warps 8-15 : dp4a (fma pipe), cols 128..255 (4 rows x 16 cols per thread)
// 6 smem stages = 3 pair-slots; ONE __syncthreads per 2 chunks.
// ============================================================================
__device__ __forceinline__ void load_pair(uint32_t sb, const int8_t* Ag, const int8_t* Bg,
                                          int pair, int tid) {
    const int s0 = (pair % 3) * 2;
    const int k0 = pair * 2 * BK;
    #pragma unroll
    for (int j = 0; j < PAIR_SEGS / NTHREADS; ++j) {   // 3072/512 = 6
        int seg = tid + NTHREADS * j;
        int half = (seg >= PAIR_SEGS / 2);
        int seg1 = seg - half * (PAIR_SEGS / 2);
        int s = s0 + half;
        int kh = k0 + half * BK;
        int r = seg1 >> 2, c = seg1 & 3;
        if (r < BM) {
            cpa16(sb + s * A_STAGE + SWZ64(r, c),
                  Ag + (size_t)r * K_DIM + kh + c * 16);
        } else {
            int br = r - BM;
            cpa16(sb + SMEM_B_OFF + s * B_STAGE + SWZ64(br, c),
                  Bg + (size_t)br * K_DIM + kh + c * 16);
        }
    }
}

__global__ void __launch_bounds__(NTHREADS, 1)
hq_gemm(float* __restrict__ out, float k1) {
    extern __shared__ char smem[];
    const uint32_t sb = smem_u32(smem);
    const int tid = threadIdx.x;
    const int wid = tid >> 5, lane = tid & 31;

    const int m0 = blockIdx.y * BM;
    const int n0 = blockIdx.x * BN;

    const int8_t* Ag = g_zx + (size_t)m0 * K_DIM;
    const int8_t* Bg = g_zw + (size_t)n0 * K_DIM;

    load_pair(sb, Ag, Bg, 0, tid);
    asm volatile("cp.async.commit_group;" ::: "memory");

    if (wid < 8) {
        // ==================== tensor warps ====================
        const int warpM = wid & 3, warpN = wid >> 2;

        const int arow = warpM * 32 + (lane & 7) + ((lane >> 3) & 1) * 8;
        const int acadd = (lane >> 4) & 1;
        const int axor = (arow >> 1) & 3;
        const int brow = warpN * 64 + (lane & 7) + ((lane >> 4) & 1) * 8;
        const int bcadd = (lane >> 3) & 1;
        const int bxor = (brow >> 1) & 3;

        int acc[64];
        #pragma unroll
        for (int i = 0; i < 64; ++i) acc[i] = 0;

        for (int p = 0; p < NPAIR; ++p) {
            if (p + 1 < NPAIR) {
                load_pair(sb, Ag, Bg, p + 1, tid);
                asm volatile("cp.async.commit_group;" ::: "memory");
                asm volatile("cp.async.wait_group 1;" ::: "memory");
            } else {
                asm volatile("cp.async.wait_group 0;" ::: "memory");
            }
            __syncthreads();   // pair p visible; pair p-2's slot now free

            #pragma unroll
            for (int h = 0; h < 2; ++h) {
                uint32_t aS = sb + ((p % 3) * 2 + h) * A_STAGE;
                uint32_t bS = sb + SMEM_B_OFF + ((p % 3) * 2 + h) * B_STAGE;
                #pragma unroll
                for (int kk = 0; kk < 2; ++kk) {
                    uint32_t af[8], bf[16];
                    #pragma unroll
                    for (int ma = 0; ma < 2; ++ma)
                        ldm4(aS + (uint32_t)(arow + ma * 16) * 64 +
                                 (uint32_t)(((2 * kk + acadd) ^ axor) << 4),
                             af[4*ma], af[4*ma+1], af[4*ma+2], af[4*ma+3]);
                    #pragma unroll
                    for (int nb = 0; nb < 4; ++nb)
                        ldm4(bS + (uint32_t)(brow + nb * 16) * 64 +
                                 (uint32_t)(((2 * kk + bcadd) ^ bxor) << 4),
                             bf[4*nb], bf[4*nb+1], bf[4*nb+2], bf[4*nb+3]);
                    #pragma unroll
                    for (int ma = 0; ma < 2; ++ma)
                        #pragma unroll
                        for (int na = 0; na < 8; ++na)
                            mma_s8(acc + (ma * 8 + na) * 4, af + 4 * ma,
                                   bf[(na >> 1) * 4 + (na & 1) * 2],
                                   bf[(na >> 1) * 4 + (na & 1) * 2 + 1]);
                }
            }
        }

        #pragma unroll
        for (int ma = 0; ma < 2; ++ma) {
            int r0 = m0 + warpM * 32 + ma * 16 + (lane >> 2);
            float al0 = g_alpha[r0], al1 = g_alpha[r0 + 8];
            float* o0 = out + (size_t)r0 * N_COLS;
            float* o1 = out + (size_t)(r0 + 8) * N_COLS;
            #pragma unroll
            for (int na = 0; na < 8; ++na) {
                int col = n0 + warpN * 64 + na * 8 + (lane & 3) * 2;
                float b0 = g_beta[col], b1 = g_beta[col + 1];
                const int* d = acc + (ma * 8 + na) * 4;
                float2 p0, p1;
                p0.x = fmaf(k1, (float)d[0], al0 + b0);
                p0.y = fmaf(k1, (float)d[1], al0 + b1);
                p1.x = fmaf(k1, (float)d[2], al1 + b0);
                p1.y = fmaf(k1, (float)d[3], al1 + b1);
                *(float2*)(o0 + col) = p0;
                *(float2*)(o1 + col) = p1;
            }
        }
    } else {
        // ===== dp4a warps: 128 cols, 4 rows x 16 cols per thread =====
        const int dwid = wid - 8;
        const int warpMd = dwid & 3;                     // 4 groups x 32 rows
        const int warpNd = dwid >> 2;                    // 2 groups x 64 cols
        const int dr0 = warpMd * 32 + (lane >> 2);       // rows dr0 + 8i
        const int db0 = BNT + warpNd * 64 + (lane & 3);  // tile cols db0 + 4j

        int acc2[64];
        #pragma unroll
        for (int i = 0; i < 64; ++i) acc2[i] = 0;

        for (int p = 0; p < NPAIR; ++p) {
            if (p + 1 < NPAIR) {
                load_pair(sb, Ag, Bg, p + 1, tid);
                asm volatile("cp.async.commit_group;" ::: "memory");
                asm volatile("cp.async.wait_group 1;" ::: "memory");
            } else {
                asm volatile("cp.async.wait_group 0;" ::: "memory");
            }
            __syncthreads();

            #pragma unroll
            for (int h = 0; h < 2; ++h) {
                uint32_t aS = sb + ((p % 3) * 2 + h) * A_STAGE;
                uint32_t bS = sb + SMEM_B_OFF + ((p % 3) * 2 + h) * B_STAGE;
                #pragma unroll
                for (int kb = 0; kb < 4; ++kb) {
                    uint4 aw[4];
                    #pragma unroll
                    for (int i = 0; i < 4; ++i) {
                        int r = dr0 + 8 * i;
                        aw[i] = lds128(aS + ((uint32_t)r << 6) +
                                       (uint32_t)((kb ^ ((r >> 1) & 3)) << 4));
                    }
                    #pragma unroll
                    for (int j = 0; j < 16; ++j) {
                        int r = db0 + 4 * j;
                        uint4 bw = lds128(bS + ((uint32_t)r << 6) +
                                          (uint32_t)((kb ^ ((r >> 1) & 3)) << 4));
                        #pragma unroll
                        for (int i = 0; i < 4; ++i) {
                            int a0 = acc2[i * 16 + j];
                            a0 = dp4a_s(aw[i].x, bw.x, a0);
                            a0 = dp4a_s(aw[i].y, bw.y, a0);
                            a0 = dp4a_s(aw[i].z, bw.z, a0);
                            acc2[i * 16 + j] = dp4a_s(aw[i].w, bw.w, a0);
                        }
                    }
                }
            }
        }

        #pragma unroll
        for (int i = 0; i < 4; ++i) {
            int row = m0 + dr0 + 8 * i;
            float al = g_alpha[row];
            float* orow = out + (size_t)row * N_COLS;
            #pragma unroll
            for (int j = 0; j < 16; ++j) {
                int col = n0 + db0 + 4 * j;
                orow[col] = fmaf(k1, (float)acc2[i * 16 + j], al + g_beta[col]);
            }
        }
    }
}

// ============================================================================
extern "C" void kernel_launch(void* const* d_in, const int* in_sizes, int n_in,
                              void* d_out, int out_size) {
    const float* x = (const float*)d_in[0];
    const float* w = (const float*)d_in[1];
    const float* bias = (const float*)d_in[2];
    float* out = (float*)d_out;

    const float scale = 768.0f / 255.0f;
    const float cc = -384.0f + 128.0f * scale;        // = 384/255
    const float k1 = scale * scale / (float)PADDED;
    const float kA = scale * cc / (float)PADDED;
    const float c2 = cc * cc;

    hq_fwht_quant<<<M_ROWS + N_COLS, 256>>>(x, w, bias, kA, c2);

    static_assert(SMEM_TOTAL == 147456, "smem");
    cudaFuncSetAttribute(hq_gemm, cudaFuncAttributeMaxDynamicSharedMemorySize, SMEM_TOTAL);
    dim3 grid(N_COLS / BN, M_ROWS / BM);              // 16 x 64
    hq_gemm<<<grid, NTHREADS, SMEM_TOTAL>>>(out, k1);
}